// round 1
// baseline (speedup 1.0000x reference)
#include <cuda_runtime.h>
#include <cuda_bf16.h>
#include <math.h>

// Problem constants
#define BATCH  2
#define LSEQ   2304          // 48*48
#define CDIM   512
#define NH     8
#define NKV    4
#define HD     64
#define BL     (BATCH*LSEQ)  // 4608
#define KVDIM  (NKV*HD)      // 256

// Scratch (device globals; no allocation allowed)
__device__ float g_q[(size_t)BL * CDIM];     // 9.4 MB
__device__ float g_k[(size_t)BL * KVDIM];    // 4.7 MB
__device__ float g_v[(size_t)BL * KVDIM];    // 4.7 MB
__device__ float g_attn[(size_t)BL * CDIM];  // 9.4 MB

// ---------------------------------------------------------------------------
// Tiled fp32 GEMM: C[M,N] = A[M,K] @ B[K,N], row-major, all dims divisible.
// BM=BN=64, BK=16, 16x16 threads, 4x4 microtile per thread.
// ---------------------------------------------------------------------------
__global__ __launch_bounds__(256) void gemm_kernel(
    const float* __restrict__ A, const float* __restrict__ B,
    float* __restrict__ C, int M, int N, int K)
{
    const int BM = 64, BN = 64, BK = 16, TM = 4, TN = 4;
    __shared__ float As[BK][BM];
    __shared__ float Bs[BK][BN];

    int tx = threadIdx.x;          // 0..15
    int ty = threadIdx.y;          // 0..15
    int tid = ty * 16 + tx;
    int blockRow = blockIdx.y * BM;
    int blockCol = blockIdx.x * BN;

    float acc[TM][TN];
#pragma unroll
    for (int i = 0; i < TM; i++)
#pragma unroll
        for (int j = 0; j < TN; j++) acc[i][j] = 0.f;

    for (int k0 = 0; k0 < K; k0 += BK) {
        // Load A tile (BM x BK) transposed into As[BK][BM]
#pragma unroll
        for (int i = tid; i < BM * BK; i += 256) {
            int r = i / BK, c = i % BK;
            As[c][r] = A[(size_t)(blockRow + r) * K + k0 + c];
        }
        // Load B tile (BK x BN)
#pragma unroll
        for (int i = tid; i < BK * BN; i += 256) {
            int r = i / BN, c = i % BN;
            Bs[r][c] = B[(size_t)(k0 + r) * N + blockCol + c];
        }
        __syncthreads();

#pragma unroll
        for (int kk = 0; kk < BK; kk++) {
            float a[TM], b[TN];
#pragma unroll
            for (int i = 0; i < TM; i++) a[i] = As[kk][ty * TM + i];
#pragma unroll
            for (int j = 0; j < TN; j++) b[j] = Bs[kk][tx * TN + j];
#pragma unroll
            for (int i = 0; i < TM; i++)
#pragma unroll
                for (int j = 0; j < TN; j++) acc[i][j] += a[i] * b[j];
        }
        __syncthreads();
    }

#pragma unroll
    for (int i = 0; i < TM; i++)
#pragma unroll
        for (int j = 0; j < TN; j++)
            C[(size_t)(blockRow + ty * TM + i) * N + blockCol + tx * TN + j] = acc[i][j];
}

// ---------------------------------------------------------------------------
// Fused RMSNorm + RoPE over one (row, head). 64 threads per block.
// X layout: [BL, nHeads*64]; pos = row % LSEQ.
// ---------------------------------------------------------------------------
__global__ __launch_bounds__(64) void norm_rope_kernel(
    float* __restrict__ X, const float* __restrict__ w, int nHeads)
{
    int row = blockIdx.x;
    int h   = blockIdx.y;
    int pos = row % LSEQ;
    float* p = X + (size_t)row * (nHeads * HD) + h * HD;
    int t = threadIdx.x;   // 0..63

    __shared__ float sv[HD];
    __shared__ float red[HD];

    float v = p[t];
    red[t] = v * v;
    __syncthreads();
#pragma unroll
    for (int s = 32; s > 0; s >>= 1) {
        if (t < s) red[t] += red[t + s];
        __syncthreads();
    }
    float inv = rsqrtf(red[0] * (1.0f / HD) + 1e-6f);
    sv[t] = v * inv * w[t];
    __syncthreads();

    if (t < 32) {
        float x1 = sv[t], x2 = sv[t + 32];
        // inv_freq = 10000^(-t/32)
        float inv_freq = powf(10000.0f, -(float)t / 32.0f);
        float ang = (float)pos * inv_freq;
        float s, c;
        sincosf(ang, &s, &c);   // precise variant: args up to ~2300 rad
        p[t]      = x1 * c - x2 * s;
        p[t + 32] = x1 * s + x2 * c;
    }
}

// ---------------------------------------------------------------------------
// Flash attention, fp32: block = (64 queries) x (one head) x (one batch).
// 256 threads as 16x16; 4x4 microtiles for both QK^T and P@V.
// Dynamic smem: Qs(64x64) + KVs(64x64) + Ss(64x64) + m/l/alpha(3x64).
// ---------------------------------------------------------------------------
#define QT 64
#define KT 64
#define ATTN_SMEM ((QT*HD + KT*HD + QT*KT + 3*QT) * sizeof(float))

__global__ __launch_bounds__(256) void attn_kernel(
    const float* __restrict__ Q, const float* __restrict__ K,
    const float* __restrict__ V, float* __restrict__ O)
{
    extern __shared__ float sm[];
    float* Qs   = sm;                       // QT*HD
    float* KVs  = Qs + QT * HD;             // KT*HD (K, then reused for V)
    float* Ss   = KVs + KT * HD;            // QT*KT (scores -> probs)
    float* mrow = Ss + QT * KT;             // QT
    float* lrow = mrow + QT;                // QT
    float* arow = lrow + QT;                // QT

    int qt  = blockIdx.x;          // 0..35
    int h   = blockIdx.y;          // 0..7
    int b   = blockIdx.z;          // 0..1
    int kvh = h >> 1;              // GQA: 2 q-heads per kv-head
    int tid = threadIdx.x;
    int tx  = tid & 15, ty = tid >> 4;
    int q0  = qt * QT;

    const float scale = 0.125f;    // 1/sqrt(64)

    // Load Q tile
    for (int i = tid; i < QT * HD; i += 256) {
        int r = i >> 6, c = i & 63;
        Qs[i] = Q[(size_t)(b * LSEQ + q0 + r) * CDIM + h * HD + c];
    }
    if (tid < QT) { mrow[tid] = -1e30f; lrow[tid] = 0.f; }
    __syncthreads();

    float acc[4][4];
#pragma unroll
    for (int i = 0; i < 4; i++)
#pragma unroll
        for (int j = 0; j < 4; j++) acc[i][j] = 0.f;

    for (int k0 = 0; k0 < LSEQ; k0 += KT) {
        // Load K tile
        for (int i = tid; i < KT * HD; i += 256) {
            int r = i >> 6, c = i & 63;
            KVs[i] = K[(size_t)(b * LSEQ + k0 + r) * KVDIM + kvh * HD + c];
        }
        __syncthreads();

        // S = scale * Q @ K^T  (4x4 per thread)
        {
            float s[4][4];
#pragma unroll
            for (int i = 0; i < 4; i++)
#pragma unroll
                for (int j = 0; j < 4; j++) s[i][j] = 0.f;
#pragma unroll 8
            for (int d = 0; d < HD; d++) {
                float qv[4], kv[4];
#pragma unroll
                for (int i = 0; i < 4; i++) qv[i] = Qs[(ty * 4 + i) * HD + d];
#pragma unroll
                for (int j = 0; j < 4; j++) kv[j] = KVs[(tx * 4 + j) * HD + d];
#pragma unroll
                for (int i = 0; i < 4; i++)
#pragma unroll
                    for (int j = 0; j < 4; j++) s[i][j] += qv[i] * kv[j];
            }
#pragma unroll
            for (int i = 0; i < 4; i++)
#pragma unroll
                for (int j = 0; j < 4; j++)
                    Ss[(ty * 4 + i) * KT + tx * 4 + j] = s[i][j] * scale;
        }
        __syncthreads();

        // Online softmax update: one thread per query row
        if (tid < QT) {
            float m_old = mrow[tid];
            float tm = m_old;
#pragma unroll 8
            for (int k = 0; k < KT; k++) tm = fmaxf(tm, Ss[tid * KT + k]);
            float a = __expf(m_old - tm);
            float tsum = 0.f;
#pragma unroll 8
            for (int k = 0; k < KT; k++) {
                float pexp = __expf(Ss[tid * KT + k] - tm);
                Ss[tid * KT + k] = pexp;
                tsum += pexp;
            }
            lrow[tid] = lrow[tid] * a + tsum;
            mrow[tid] = tm;
            arow[tid] = a;
        }
        __syncthreads();

        // Rescale accumulators; reload KVs with V tile
#pragma unroll
        for (int i = 0; i < 4; i++) {
            float a = arow[ty * 4 + i];
#pragma unroll
            for (int j = 0; j < 4; j++) acc[i][j] *= a;
        }
        for (int i = tid; i < KT * HD; i += 256) {
            int r = i >> 6, c = i & 63;
            KVs[i] = V[(size_t)(b * LSEQ + k0 + r) * KVDIM + kvh * HD + c];
        }
        __syncthreads();

        // acc += P @ V  (4x4 per thread)
#pragma unroll 8
        for (int kk = 0; kk < KT; kk++) {
            float pv[4], vv[4];
#pragma unroll
            for (int i = 0; i < 4; i++) pv[i] = Ss[(ty * 4 + i) * KT + kk];
#pragma unroll
            for (int j = 0; j < 4; j++) vv[j] = KVs[kk * HD + tx * 4 + j];
#pragma unroll
            for (int i = 0; i < 4; i++)
#pragma unroll
                for (int j = 0; j < 4; j++) acc[i][j] += pv[i] * vv[j];
        }
        __syncthreads();
    }

    // Finalize: divide by l, write (b, q, h, d) -> [BL, CDIM]
#pragma unroll
    for (int i = 0; i < 4; i++) {
        float invl = 1.0f / lrow[ty * 4 + i];
#pragma unroll
        for (int j = 0; j < 4; j++)
            O[(size_t)(b * LSEQ + q0 + ty * 4 + i) * CDIM + h * HD + tx * 4 + j] =
                acc[i][j] * invl;
    }
}

// ---------------------------------------------------------------------------
extern "C" void kernel_launch(void* const* d_in, const int* in_sizes, int n_in,
                              void* d_out, int out_size)
{
    const float* x   = (const float*)d_in[0];
    const float* wq  = (const float*)d_in[1];
    const float* wk  = (const float*)d_in[2];
    const float* wv  = (const float*)d_in[3];
    const float* wo  = (const float*)d_in[4];
    const float* qnw = (const float*)d_in[5];
    const float* knw = (const float*)d_in[6];
    float* out = (float*)d_out;

    float *pq, *pk, *pv, *pa;
    cudaGetSymbolAddress((void**)&pq, g_q);
    cudaGetSymbolAddress((void**)&pk, g_k);
    cudaGetSymbolAddress((void**)&pv, g_v);
    cudaGetSymbolAddress((void**)&pa, g_attn);

    dim3 tb(16, 16);

    // QKV projections
    gemm_kernel<<<dim3(CDIM / 64, BL / 64), tb>>>(x, wq, pq, BL, CDIM, CDIM);
    gemm_kernel<<<dim3(KVDIM / 64, BL / 64), tb>>>(x, wk, pk, BL, KVDIM, CDIM);
    gemm_kernel<<<dim3(KVDIM / 64, BL / 64), tb>>>(x, wv, pv, BL, KVDIM, CDIM);

    // RMSNorm + RoPE
    norm_rope_kernel<<<dim3(BL, NH), 64>>>(pq, qnw, NH);
    norm_rope_kernel<<<dim3(BL, NKV), 64>>>(pk, knw, NKV);

    // Attention
    cudaFuncSetAttribute(attn_kernel, cudaFuncAttributeMaxDynamicSharedMemorySize,
                         (int)ATTN_SMEM);
    attn_kernel<<<dim3(LSEQ / QT, NH, BATCH), 256, ATTN_SMEM>>>(pq, pk, pv, pa);

    // Output projection
    gemm_kernel<<<dim3(CDIM / 64, BL / 64), tb>>>(pa, wo, out, BL, CDIM, CDIM);
}

// round 2
// speedup vs baseline: 6.0788x; 6.0788x over previous
#include <cuda_runtime.h>
#include <cuda_bf16.h>
#include <math.h>

// Problem constants
#define BATCH  2
#define LSEQ   2304          // 48*48
#define CDIM   512
#define NH     8
#define NKV    4
#define HD     64
#define BL     (BATCH*LSEQ)  // 4608
#define KVDIM  (NKV*HD)      // 256

// Scratch (device globals; no allocation allowed)
__device__ float g_q[(size_t)BL * CDIM];
__device__ float g_k[(size_t)BL * KVDIM];
__device__ float g_v[(size_t)BL * KVDIM];
__device__ float g_attn[(size_t)BL * CDIM];

// ---------------------------------------------------------------------------
// mma.m16n8k8 tf32 helpers
// ---------------------------------------------------------------------------
__device__ __forceinline__ unsigned f2tf32(float x) {
    unsigned r;
    asm("cvt.rna.tf32.f32 %0, %1;" : "=r"(r) : "f"(x));
    return r;
}

__device__ __forceinline__ void mma_tf32(float c[4], const unsigned a[4],
                                         const unsigned b[2]) {
    asm volatile(
        "mma.sync.aligned.m16n8k8.row.col.f32.tf32.tf32.f32 "
        "{%0,%1,%2,%3}, {%4,%5,%6,%7}, {%8,%9}, {%0,%1,%2,%3};"
        : "+f"(c[0]), "+f"(c[1]), "+f"(c[2]), "+f"(c[3])
        : "r"(a[0]), "r"(a[1]), "r"(a[2]), "r"(a[3]), "r"(b[0]), "r"(b[1]));
}

// ---------------------------------------------------------------------------
// tf32 GEMM: C[M,N] = A[M,K] @ B[K,N], row-major. BM=BN=64, BK=16.
// 128 threads = 4 warps (2x2), each warp 32x32 = 2 m-tiles x 4 n-tiles.
// ---------------------------------------------------------------------------
#define ALD 20   // As row stride (16+4 pad)
#define BLD 68   // Bs row stride (64+4 pad)

__global__ __launch_bounds__(128) void gemm_tf32_kernel(
    const float* __restrict__ A, const float* __restrict__ B,
    float* __restrict__ C, int M, int N, int K)
{
    __shared__ float As[64 * ALD];
    __shared__ float Bs[16 * BLD];

    int tid = threadIdx.x;
    int lane = tid & 31;
    int warp = tid >> 5;
    int wm = warp >> 1;          // 0..1
    int wn = warp & 1;           // 0..1
    int gid = lane >> 2;         // group id 0..7
    int q4  = lane & 3;          // thread in group

    int bR = blockIdx.y * 64;
    int bC = blockIdx.x * 64;

    float acc[2][4][4];
#pragma unroll
    for (int mi = 0; mi < 2; mi++)
#pragma unroll
        for (int nj = 0; nj < 4; nj++)
#pragma unroll
            for (int e = 0; e < 4; e++) acc[mi][nj][e] = 0.f;

    for (int k0 = 0; k0 < K; k0 += 16) {
        // Load A tile 64x16 (256 float4), B tile 16x64 (256 float4)
#pragma unroll
        for (int i = tid; i < 256; i += 128) {
            int r = i >> 2, c4 = (i & 3) * 4;
            float4 v = *(const float4*)&A[(size_t)(bR + r) * K + k0 + c4];
            As[r * ALD + c4 + 0] = __uint_as_float(f2tf32(v.x));
            As[r * ALD + c4 + 1] = __uint_as_float(f2tf32(v.y));
            As[r * ALD + c4 + 2] = __uint_as_float(f2tf32(v.z));
            As[r * ALD + c4 + 3] = __uint_as_float(f2tf32(v.w));
        }
#pragma unroll
        for (int i = tid; i < 256; i += 128) {
            int r = i >> 4, c4 = (i & 15) * 4;
            float4 v = *(const float4*)&B[(size_t)(k0 + r) * N + bC + c4];
            Bs[r * BLD + c4 + 0] = __uint_as_float(f2tf32(v.x));
            Bs[r * BLD + c4 + 1] = __uint_as_float(f2tf32(v.y));
            Bs[r * BLD + c4 + 2] = __uint_as_float(f2tf32(v.z));
            Bs[r * BLD + c4 + 3] = __uint_as_float(f2tf32(v.w));
        }
        __syncthreads();

#pragma unroll
        for (int t = 0; t < 2; t++) {
            unsigned af[2][4], bf[4][2];
#pragma unroll
            for (int mi = 0; mi < 2; mi++) {
                int rb = wm * 32 + mi * 16 + gid;
                af[mi][0] = __float_as_uint(As[rb * ALD + t * 8 + q4]);
                af[mi][1] = __float_as_uint(As[(rb + 8) * ALD + t * 8 + q4]);
                af[mi][2] = __float_as_uint(As[rb * ALD + t * 8 + 4 + q4]);
                af[mi][3] = __float_as_uint(As[(rb + 8) * ALD + t * 8 + 4 + q4]);
            }
#pragma unroll
            for (int nj = 0; nj < 4; nj++) {
                int cb = wn * 32 + nj * 8 + gid;
                bf[nj][0] = __float_as_uint(Bs[(t * 8 + q4) * BLD + cb]);
                bf[nj][1] = __float_as_uint(Bs[(t * 8 + 4 + q4) * BLD + cb]);
            }
#pragma unroll
            for (int mi = 0; mi < 2; mi++)
#pragma unroll
                for (int nj = 0; nj < 4; nj++)
                    mma_tf32(acc[mi][nj], af[mi], bf[nj]);
        }
        __syncthreads();
    }

    // Store
#pragma unroll
    for (int mi = 0; mi < 2; mi++) {
        int r0 = bR + wm * 32 + mi * 16 + gid;
#pragma unroll
        for (int nj = 0; nj < 4; nj++) {
            int c = bC + wn * 32 + nj * 8 + 2 * q4;
            *(float2*)&C[(size_t)r0 * N + c] =
                make_float2(acc[mi][nj][0], acc[mi][nj][1]);
            *(float2*)&C[(size_t)(r0 + 8) * N + c] =
                make_float2(acc[mi][nj][2], acc[mi][nj][3]);
        }
    }
}

// ---------------------------------------------------------------------------
// Fused RMSNorm + RoPE over one (row, head). 64 threads per block.
// ---------------------------------------------------------------------------
__global__ __launch_bounds__(64) void norm_rope_kernel(
    float* __restrict__ X, const float* __restrict__ w, int nHeads)
{
    int row = blockIdx.x;
    int h   = blockIdx.y;
    int pos = row % LSEQ;
    float* p = X + (size_t)row * (nHeads * HD) + h * HD;
    int t = threadIdx.x;

    __shared__ float sv[HD];
    __shared__ float red[HD];

    float v = p[t];
    red[t] = v * v;
    __syncthreads();
#pragma unroll
    for (int s = 32; s > 0; s >>= 1) {
        if (t < s) red[t] += red[t + s];
        __syncthreads();
    }
    float inv = rsqrtf(red[0] * (1.0f / HD) + 1e-6f);
    sv[t] = v * inv * w[t];
    __syncthreads();

    if (t < 32) {
        float x1 = sv[t], x2 = sv[t + 32];
        float inv_freq = powf(10000.0f, -(float)t / 32.0f);
        float ang = (float)pos * inv_freq;
        float s, c;
        sincosf(ang, &s, &c);
        p[t]      = x1 * c - x2 * s;
        p[t + 32] = x1 * s + x2 * c;
    }
}

// ---------------------------------------------------------------------------
// Flash attention, tf32 tensor cores.
// Block = 64 queries x (head, batch). 128 threads = 4 warps; each warp owns
// 16 query rows. Softmax fully in registers (quad shfl reductions).
// Smem: Ks[64][68] + Vs[64][68] + Ss[64][68] (Q staging, then P).
// ---------------------------------------------------------------------------
#define SLD 68
#define ATTN_SMEM (3 * 64 * SLD * sizeof(float))

__global__ __launch_bounds__(128) void attn_kernel(
    const float* __restrict__ Q, const float* __restrict__ K,
    const float* __restrict__ V, float* __restrict__ O)
{
    extern __shared__ float sm[];
    float* Ks = sm;                 // 64*SLD
    float* Vs = Ks + 64 * SLD;      // 64*SLD
    float* Ss = Vs + 64 * SLD;      // 64*SLD  (Q staging, then P)

    int tid  = threadIdx.x;
    int lane = tid & 31;
    int warp = tid >> 5;
    int gid  = lane >> 2;
    int q4   = lane & 3;

    int qt = blockIdx.x, h = blockIdx.y, b = blockIdx.z;
    int kvh = h >> 1;
    int q0  = qt * 64;
    int r0  = warp * 16 + gid;      // this thread's first query row (local)

    // Stage Q tile (scaled by 1/sqrt(hd), tf32-rounded) into Ss
    for (int i = tid; i < 64 * 64; i += 128) {
        int r = i >> 6, c = i & 63;
        float qv = Q[(size_t)(b * LSEQ + q0 + r) * CDIM + h * HD + c] * 0.125f;
        Ss[r * SLD + c] = __uint_as_float(f2tf32(qv));
    }
    __syncthreads();

    // Q fragments in registers: 8 k-steps x 4 regs
    unsigned qf[8][4];
#pragma unroll
    for (int t = 0; t < 8; t++) {
        qf[t][0] = __float_as_uint(Ss[r0 * SLD + t * 8 + q4]);
        qf[t][1] = __float_as_uint(Ss[(r0 + 8) * SLD + t * 8 + q4]);
        qf[t][2] = __float_as_uint(Ss[r0 * SLD + t * 8 + 4 + q4]);
        qf[t][3] = __float_as_uint(Ss[(r0 + 8) * SLD + t * 8 + 4 + q4]);
    }
    __syncthreads();

    float oacc[8][4];
#pragma unroll
    for (int j = 0; j < 8; j++)
#pragma unroll
        for (int e = 0; e < 4; e++) oacc[j][e] = 0.f;
    float m0 = -1e30f, m1 = -1e30f, l0 = 0.f, l1 = 0.f;

    for (int k0 = 0; k0 < LSEQ; k0 += 64) {
        // Load K and V tiles (64x64 each) with tf32 rounding
#pragma unroll
        for (int i = tid; i < 1024; i += 128) {
            int r = i >> 4, c4 = (i & 15) * 4;
            float4 kv = *(const float4*)&K[(size_t)(b * LSEQ + k0 + r) * KVDIM + kvh * HD + c4];
            Ks[r * SLD + c4 + 0] = __uint_as_float(f2tf32(kv.x));
            Ks[r * SLD + c4 + 1] = __uint_as_float(f2tf32(kv.y));
            Ks[r * SLD + c4 + 2] = __uint_as_float(f2tf32(kv.z));
            Ks[r * SLD + c4 + 3] = __uint_as_float(f2tf32(kv.w));
            float4 vv = *(const float4*)&V[(size_t)(b * LSEQ + k0 + r) * KVDIM + kvh * HD + c4];
            Vs[r * SLD + c4 + 0] = __uint_as_float(f2tf32(vv.x));
            Vs[r * SLD + c4 + 1] = __uint_as_float(f2tf32(vv.y));
            Vs[r * SLD + c4 + 2] = __uint_as_float(f2tf32(vv.z));
            Vs[r * SLD + c4 + 3] = __uint_as_float(f2tf32(vv.w));
        }
        __syncthreads();

        // S = (scaled Q) @ K^T : 8 n-tiles of 8 keys
        float s[8][4];
#pragma unroll
        for (int j = 0; j < 8; j++)
#pragma unroll
            for (int e = 0; e < 4; e++) s[j][e] = 0.f;
#pragma unroll
        for (int t = 0; t < 8; t++) {
#pragma unroll
            for (int j = 0; j < 8; j++) {
                unsigned bf[2];
                bf[0] = __float_as_uint(Ks[(j * 8 + gid) * SLD + t * 8 + q4]);
                bf[1] = __float_as_uint(Ks[(j * 8 + gid) * SLD + t * 8 + 4 + q4]);
                mma_tf32(s[j], qf[t], bf);
            }
        }

        // Online softmax in registers.
        // s[j][0],s[j][1]: row r0, cols j*8+2q4,+1 ; s[j][2],s[j][3]: row r0+8.
        float mt0 = -1e30f, mt1 = -1e30f;
#pragma unroll
        for (int j = 0; j < 8; j++) {
            mt0 = fmaxf(mt0, fmaxf(s[j][0], s[j][1]));
            mt1 = fmaxf(mt1, fmaxf(s[j][2], s[j][3]));
        }
        mt0 = fmaxf(mt0, __shfl_xor_sync(0xffffffffu, mt0, 1));
        mt0 = fmaxf(mt0, __shfl_xor_sync(0xffffffffu, mt0, 2));
        mt1 = fmaxf(mt1, __shfl_xor_sync(0xffffffffu, mt1, 1));
        mt1 = fmaxf(mt1, __shfl_xor_sync(0xffffffffu, mt1, 2));

        float mn0 = fmaxf(m0, mt0), mn1 = fmaxf(m1, mt1);
        float a0 = __expf(m0 - mn0), a1 = __expf(m1 - mn1);
        m0 = mn0; m1 = mn1;

        float ps0 = 0.f, ps1 = 0.f;
#pragma unroll
        for (int j = 0; j < 8; j++) {
            s[j][0] = __expf(s[j][0] - m0);
            s[j][1] = __expf(s[j][1] - m0);
            s[j][2] = __expf(s[j][2] - m1);
            s[j][3] = __expf(s[j][3] - m1);
            ps0 += s[j][0] + s[j][1];
            ps1 += s[j][2] + s[j][3];
        }
        ps0 += __shfl_xor_sync(0xffffffffu, ps0, 1);
        ps0 += __shfl_xor_sync(0xffffffffu, ps0, 2);
        ps1 += __shfl_xor_sync(0xffffffffu, ps1, 1);
        ps1 += __shfl_xor_sync(0xffffffffu, ps1, 2);
        l0 = l0 * a0 + ps0;
        l1 = l1 * a1 + ps1;

#pragma unroll
        for (int j = 0; j < 8; j++) {
            oacc[j][0] *= a0; oacc[j][1] *= a0;
            oacc[j][2] *= a1; oacc[j][3] *= a1;
        }

        // Store P (tf32) into Ss for the PV mma layout conversion.
        // Each warp writes/reads only its own 16 rows -> syncwarp suffices.
#pragma unroll
        for (int j = 0; j < 8; j++) {
            *(float2*)&Ss[r0 * SLD + j * 8 + 2 * q4] = make_float2(
                __uint_as_float(f2tf32(s[j][0])), __uint_as_float(f2tf32(s[j][1])));
            *(float2*)&Ss[(r0 + 8) * SLD + j * 8 + 2 * q4] = make_float2(
                __uint_as_float(f2tf32(s[j][2])), __uint_as_float(f2tf32(s[j][3])));
        }
        __syncwarp();

        // O += P @ V : k over 64 keys (8 steps), 8 d-tiles
#pragma unroll
        for (int t = 0; t < 8; t++) {
            unsigned af[4];
            af[0] = __float_as_uint(Ss[r0 * SLD + t * 8 + q4]);
            af[1] = __float_as_uint(Ss[(r0 + 8) * SLD + t * 8 + q4]);
            af[2] = __float_as_uint(Ss[r0 * SLD + t * 8 + 4 + q4]);
            af[3] = __float_as_uint(Ss[(r0 + 8) * SLD + t * 8 + 4 + q4]);
#pragma unroll
            for (int j = 0; j < 8; j++) {
                unsigned bf[2];
                bf[0] = __float_as_uint(Vs[(t * 8 + q4) * SLD + j * 8 + gid]);
                bf[1] = __float_as_uint(Vs[(t * 8 + 4 + q4) * SLD + j * 8 + gid]);
                mma_tf32(oacc[j], af, bf);
            }
        }
        __syncthreads();   // before next K/V tile overwrite
    }

    // Finalize and write O
    float il0 = 1.0f / l0, il1 = 1.0f / l1;
#pragma unroll
    for (int j = 0; j < 8; j++) {
        int c = h * HD + j * 8 + 2 * q4;
        *(float2*)&O[(size_t)(b * LSEQ + q0 + r0) * CDIM + c] =
            make_float2(oacc[j][0] * il0, oacc[j][1] * il0);
        *(float2*)&O[(size_t)(b * LSEQ + q0 + r0 + 8) * CDIM + c] =
            make_float2(oacc[j][2] * il1, oacc[j][3] * il1);
    }
}

// ---------------------------------------------------------------------------
extern "C" void kernel_launch(void* const* d_in, const int* in_sizes, int n_in,
                              void* d_out, int out_size)
{
    const float* x   = (const float*)d_in[0];
    const float* wq  = (const float*)d_in[1];
    const float* wk  = (const float*)d_in[2];
    const float* wv  = (const float*)d_in[3];
    const float* wo  = (const float*)d_in[4];
    const float* qnw = (const float*)d_in[5];
    const float* knw = (const float*)d_in[6];
    float* out = (float*)d_out;

    float *pq, *pk, *pv, *pa;
    cudaGetSymbolAddress((void**)&pq, g_q);
    cudaGetSymbolAddress((void**)&pk, g_k);
    cudaGetSymbolAddress((void**)&pv, g_v);
    cudaGetSymbolAddress((void**)&pa, g_attn);

    // QKV projections (tf32 tensor cores)
    gemm_tf32_kernel<<<dim3(CDIM / 64, BL / 64), 128>>>(x, wq, pq, BL, CDIM, CDIM);
    gemm_tf32_kernel<<<dim3(KVDIM / 64, BL / 64), 128>>>(x, wk, pk, BL, KVDIM, CDIM);
    gemm_tf32_kernel<<<dim3(KVDIM / 64, BL / 64), 128>>>(x, wv, pv, BL, KVDIM, CDIM);

    // RMSNorm + RoPE
    norm_rope_kernel<<<dim3(BL, NH), 64>>>(pq, qnw, NH);
    norm_rope_kernel<<<dim3(BL, NKV), 64>>>(pk, knw, NKV);

    // Attention
    cudaFuncSetAttribute(attn_kernel, cudaFuncAttributeMaxDynamicSharedMemorySize,
                         (int)ATTN_SMEM);
    attn_kernel<<<dim3(LSEQ / 64, NH, BATCH), 128, ATTN_SMEM>>>(pq, pk, pv, pa);

    // Output projection
    gemm_tf32_kernel<<<dim3(CDIM / 64, BL / 64), 128>>>(pa, wo, out, BL, CDIM, CDIM);
}

// round 4
// speedup vs baseline: 6.6444x; 1.0930x over previous
#include <cuda_runtime.h>
#include <cuda_bf16.h>
#include <math.h>

// Problem constants
#define BATCH  2
#define LSEQ   2304          // 48*48
#define CDIM   512
#define NH     8
#define NKV    4
#define HD     64
#define BL     (BATCH*LSEQ)  // 4608
#define QKVD   1024          // fused q(512) | k(256) | v(256)

// Scratch (device globals; no allocation allowed)
__device__ float g_qkv[(size_t)BL * QKVD];   // 18.9 MB
__device__ float g_attn[(size_t)BL * CDIM];  // 9.4 MB

// ---------------------------------------------------------------------------
// mma.m16n8k8 tf32 helpers
// ---------------------------------------------------------------------------
__device__ __forceinline__ unsigned f2tf32(float x) {
    unsigned r;
    asm("cvt.rna.tf32.f32 %0, %1;" : "=r"(r) : "f"(x));
    return r;
}
__device__ __forceinline__ float f2tf32f(float x) {
    return __uint_as_float(f2tf32(x));
}

__device__ __forceinline__ void mma_tf32(float c[4], const unsigned a[4],
                                         const unsigned b[2]) {
    asm volatile(
        "mma.sync.aligned.m16n8k8.row.col.f32.tf32.tf32.f32 "
        "{%0,%1,%2,%3}, {%4,%5,%6,%7}, {%8,%9}, {%0,%1,%2,%3};"
        : "+f"(c[0]), "+f"(c[1]), "+f"(c[2]), "+f"(c[3])
        : "r"(a[0]), "r"(a[1]), "r"(a[2]), "r"(a[3]), "r"(b[0]), "r"(b[1]));
}

// ---------------------------------------------------------------------------
// tf32 GEMM tile body: C[64,64] tile at (bR, bColC) = A[64,K] @ B[K, 64 @bColB]
// 128 threads = 4 warps (2x2), warp tile 32x32. Register-staged pipelining.
// ---------------------------------------------------------------------------
#define ALD 20   // As row stride (16+4 pad)
#define BLD 68   // Bs row stride (64+4 pad)

__device__ __forceinline__ void gemm_body(
    const float* __restrict__ A, int lda,
    const float* __restrict__ B, int ldb,
    float* __restrict__ C, int ldc,
    int K, int bR, int bColB, int bColC)
{
    __shared__ float As[64 * ALD];
    __shared__ float Bs[16 * BLD];

    int tid  = threadIdx.x;
    int lane = tid & 31;
    int warp = tid >> 5;
    int wm = warp >> 1, wn = warp & 1;
    int gid = lane >> 2, q4 = lane & 3;

    // Per-thread load coordinates (fixed across iterations)
    int ar0 = tid >> 2,  ac = (tid & 3) * 4;       // A rows tid/4, tid/4 (+32)
    int br0 = tid >> 4,  bc = (tid & 15) * 4;      // B rows tid/16 (+8)

    float acc[2][4][4];
#pragma unroll
    for (int mi = 0; mi < 2; mi++)
#pragma unroll
        for (int nj = 0; nj < 4; nj++)
#pragma unroll
            for (int e = 0; e < 4; e++) acc[mi][nj][e] = 0.f;

    // Preload k0 = 0
    float4 ast0 = *(const float4*)&A[(size_t)(bR + ar0) * lda + ac];
    float4 ast1 = *(const float4*)&A[(size_t)(bR + ar0 + 32) * lda + ac];
    float4 bst0 = *(const float4*)&B[(size_t)(br0) * ldb + bColB + bc];
    float4 bst1 = *(const float4*)&B[(size_t)(br0 + 8) * ldb + bColB + bc];

    for (int k0 = 0; k0 < K; k0 += 16) {
        // Commit staged tile to smem (tf32-rounded)
        As[ar0 * ALD + ac + 0] = f2tf32f(ast0.x);
        As[ar0 * ALD + ac + 1] = f2tf32f(ast0.y);
        As[ar0 * ALD + ac + 2] = f2tf32f(ast0.z);
        As[ar0 * ALD + ac + 3] = f2tf32f(ast0.w);
        As[(ar0 + 32) * ALD + ac + 0] = f2tf32f(ast1.x);
        As[(ar0 + 32) * ALD + ac + 1] = f2tf32f(ast1.y);
        As[(ar0 + 32) * ALD + ac + 2] = f2tf32f(ast1.z);
        As[(ar0 + 32) * ALD + ac + 3] = f2tf32f(ast1.w);
        Bs[br0 * BLD + bc + 0] = f2tf32f(bst0.x);
        Bs[br0 * BLD + bc + 1] = f2tf32f(bst0.y);
        Bs[br0 * BLD + bc + 2] = f2tf32f(bst0.z);
        Bs[br0 * BLD + bc + 3] = f2tf32f(bst0.w);
        Bs[(br0 + 8) * BLD + bc + 0] = f2tf32f(bst1.x);
        Bs[(br0 + 8) * BLD + bc + 1] = f2tf32f(bst1.y);
        Bs[(br0 + 8) * BLD + bc + 2] = f2tf32f(bst1.z);
        Bs[(br0 + 8) * BLD + bc + 3] = f2tf32f(bst1.w);
        __syncthreads();

        // Prefetch next k-tile into registers (latency hidden by mma below)
        if (k0 + 16 < K) {
            int kn = k0 + 16;
            ast0 = *(const float4*)&A[(size_t)(bR + ar0) * lda + kn + ac];
            ast1 = *(const float4*)&A[(size_t)(bR + ar0 + 32) * lda + kn + ac];
            bst0 = *(const float4*)&B[(size_t)(kn + br0) * ldb + bColB + bc];
            bst1 = *(const float4*)&B[(size_t)(kn + br0 + 8) * ldb + bColB + bc];
        }

#pragma unroll
        for (int t = 0; t < 2; t++) {
            unsigned af[2][4], bf[4][2];
#pragma unroll
            for (int mi = 0; mi < 2; mi++) {
                int rb = wm * 32 + mi * 16 + gid;
                af[mi][0] = __float_as_uint(As[rb * ALD + t * 8 + q4]);
                af[mi][1] = __float_as_uint(As[(rb + 8) * ALD + t * 8 + q4]);
                af[mi][2] = __float_as_uint(As[rb * ALD + t * 8 + 4 + q4]);
                af[mi][3] = __float_as_uint(As[(rb + 8) * ALD + t * 8 + 4 + q4]);
            }
#pragma unroll
            for (int nj = 0; nj < 4; nj++) {
                int cb = wn * 32 + nj * 8 + gid;
                bf[nj][0] = __float_as_uint(Bs[(t * 8 + q4) * BLD + cb]);
                bf[nj][1] = __float_as_uint(Bs[(t * 8 + 4 + q4) * BLD + cb]);
            }
#pragma unroll
            for (int mi = 0; mi < 2; mi++)
#pragma unroll
                for (int nj = 0; nj < 4; nj++)
                    mma_tf32(acc[mi][nj], af[mi], bf[nj]);
        }
        __syncthreads();
    }

#pragma unroll
    for (int mi = 0; mi < 2; mi++) {
        int r0 = bR + wm * 32 + mi * 16 + gid;
#pragma unroll
        for (int nj = 0; nj < 4; nj++) {
            int c = bColC + wn * 32 + nj * 8 + 2 * q4;
            *(float2*)&C[(size_t)r0 * ldc + c] =
                make_float2(acc[mi][nj][0], acc[mi][nj][1]);
            *(float2*)&C[(size_t)(r0 + 8) * ldc + c] =
                make_float2(acc[mi][nj][2], acc[mi][nj][3]);
        }
    }
}

// Fused QKV projection: selects wq/wk/wv by output column block.
__global__ __launch_bounds__(128) void gemm_qkv_kernel(
    const float* __restrict__ x, const float* __restrict__ wq,
    const float* __restrict__ wk, const float* __restrict__ wv,
    float* __restrict__ qkv)
{
    int bC = blockIdx.x * 64;
    int bR = blockIdx.y * 64;
    const float* B; int ldb, colB;
    if (bC < 512)      { B = wq; ldb = 512; colB = bC; }
    else if (bC < 768) { B = wk; ldb = 256; colB = bC - 512; }
    else               { B = wv; ldb = 256; colB = bC - 768; }
    gemm_body(x, CDIM, B, ldb, qkv, QKVD, CDIM, bR, colB, bC);
}

// Generic GEMM for the output projection.
__global__ __launch_bounds__(128) void gemm_out_kernel(
    const float* __restrict__ A, const float* __restrict__ B,
    float* __restrict__ C)
{
    int bC = blockIdx.x * 64;
    int bR = blockIdx.y * 64;
    gemm_body(A, CDIM, B, CDIM, C, CDIM, CDIM, bR, bC, bC);
}

// ---------------------------------------------------------------------------
// Fused RMSNorm + RoPE: one warp per (row, head-unit). 12 units per row
// (8 q-heads + 4 kv-heads), all in g_qkv. Lane t handles elems t, t+32 —
// exactly the rope pair. Pure shuffle reductions.
// ---------------------------------------------------------------------------
__global__ __launch_bounds__(256) void norm_rope_kernel(
    float* __restrict__ qkv, const float* __restrict__ qw,
    const float* __restrict__ kw)
{
    int u = blockIdx.x * 8 + (threadIdx.x >> 5);
    int lane = threadIdx.x & 31;
    int row = u / 12;
    int j   = u % 12;
    if (row >= BL) return;

    float* p; const float* w;
    if (j < 8) { p = qkv + (size_t)row * QKVD + j * HD;            w = qw; }
    else       { p = qkv + (size_t)row * QKVD + 512 + (j - 8) * HD; w = kw; }
    int pos = row % LSEQ;

    float x1 = p[lane], x2 = p[lane + 32];
    float ss = x1 * x1 + x2 * x2;
#pragma unroll
    for (int m = 16; m > 0; m >>= 1)
        ss += __shfl_xor_sync(0xffffffffu, ss, m);
    float inv = rsqrtf(ss * (1.0f / HD) + 1e-6f);
    float n1 = x1 * inv * w[lane];
    float n2 = x2 * inv * w[lane + 32];

    float inv_freq = powf(10000.0f, -(float)lane / 32.0f);
    float ang = (float)pos * inv_freq;
    float s, c;
    sincosf(ang, &s, &c);
    p[lane]      = n1 * c - n2 * s;
    p[lane + 32] = n1 * s + n2 * c;
}

// ---------------------------------------------------------------------------
// Flash attention, tf32, register-staged K/V pipelining.
// Block = 64 queries x (head, batch). 128 threads = 4 warps; warp owns 16
// query rows; softmax in registers.
// ---------------------------------------------------------------------------
#define SLD 68
#define ATTN_SMEM (3 * 64 * SLD * sizeof(float))

__global__ __launch_bounds__(128) void attn_kernel(
    const float* __restrict__ QKV, float* __restrict__ O)
{
    extern __shared__ float sm[];
    float* Ks = sm;
    float* Vs = Ks + 64 * SLD;
    float* Ss = Vs + 64 * SLD;     // Q staging, then P

    int tid  = threadIdx.x;
    int lane = tid & 31;
    int warp = tid >> 5;
    int gid  = lane >> 2;
    int q4   = lane & 3;

    int qt = blockIdx.x, h = blockIdx.y, b = blockIdx.z;
    int kvh = h >> 1;
    int q0  = qt * 64;
    int r0  = warp * 16 + gid;

    const float* base = QKV + (size_t)b * LSEQ * QKVD;
    const float* kbase = base + 512 + kvh * HD;
    const float* vbase = base + 768 + kvh * HD;

    // Stage Q tile (scaled, tf32) into Ss
    for (int i = tid; i < 64 * 64; i += 128) {
        int r = i >> 6, c = i & 63;
        Ss[r * SLD + c] = f2tf32f(base[(size_t)(q0 + r) * QKVD + h * HD + c] * 0.125f);
    }
    __syncthreads();

    unsigned qf[8][4];
#pragma unroll
    for (int t = 0; t < 8; t++) {
        qf[t][0] = __float_as_uint(Ss[r0 * SLD + t * 8 + q4]);
        qf[t][1] = __float_as_uint(Ss[(r0 + 8) * SLD + t * 8 + q4]);
        qf[t][2] = __float_as_uint(Ss[r0 * SLD + t * 8 + 4 + q4]);
        qf[t][3] = __float_as_uint(Ss[(r0 + 8) * SLD + t * 8 + 4 + q4]);
    }
    __syncthreads();

    float oacc[8][4];
#pragma unroll
    for (int j = 0; j < 8; j++)
#pragma unroll
        for (int e = 0; e < 4; e++) oacc[j][e] = 0.f;
    float m0 = -1e30f, m1 = -1e30f, l0 = 0.f, l1 = 0.f;

    // Per-thread K/V staging coordinates: 8 chunks of float4
    int sr = tid >> 4;            // row 0..7 (+8k per chunk)
    int sc = (tid & 15) * 4;      // col

    float4 kst[8], vst[8];
#pragma unroll
    for (int it = 0; it < 8; it++) {
        int r = sr + it * 8;
        kst[it] = *(const float4*)&kbase[(size_t)r * QKVD + sc];
        vst[it] = *(const float4*)&vbase[(size_t)r * QKVD + sc];
    }

    for (int k0 = 0; k0 < LSEQ; k0 += 64) {
        // Commit staged K/V tile (tf32)
#pragma unroll
        for (int it = 0; it < 8; it++) {
            int r = sr + it * 8;
            Ks[r * SLD + sc + 0] = f2tf32f(kst[it].x);
            Ks[r * SLD + sc + 1] = f2tf32f(kst[it].y);
            Ks[r * SLD + sc + 2] = f2tf32f(kst[it].z);
            Ks[r * SLD + sc + 3] = f2tf32f(kst[it].w);
            Vs[r * SLD + sc + 0] = f2tf32f(vst[it].x);
            Vs[r * SLD + sc + 1] = f2tf32f(vst[it].y);
            Vs[r * SLD + sc + 2] = f2tf32f(vst[it].z);
            Vs[r * SLD + sc + 3] = f2tf32f(vst[it].w);
        }
        __syncthreads();

        // Prefetch next K/V tile into registers
        if (k0 + 64 < LSEQ) {
#pragma unroll
            for (int it = 0; it < 8; it++) {
                int r = k0 + 64 + sr + it * 8;
                kst[it] = *(const float4*)&kbase[(size_t)r * QKVD + sc];
                vst[it] = *(const float4*)&vbase[(size_t)r * QKVD + sc];
            }
        }

        // S = (scaled Q) @ K^T
        float s[8][4];
#pragma unroll
        for (int j = 0; j < 8; j++)
#pragma unroll
            for (int e = 0; e < 4; e++) s[j][e] = 0.f;
#pragma unroll
        for (int t = 0; t < 8; t++) {
#pragma unroll
            for (int j = 0; j < 8; j++) {
                unsigned bf[2];
                bf[0] = __float_as_uint(Ks[(j * 8 + gid) * SLD + t * 8 + q4]);
                bf[1] = __float_as_uint(Ks[(j * 8 + gid) * SLD + t * 8 + 4 + q4]);
                mma_tf32(s[j], qf[t], bf);
            }
        }

        // Online softmax in registers
        float mt0 = -1e30f, mt1 = -1e30f;
#pragma unroll
        for (int j = 0; j < 8; j++) {
            mt0 = fmaxf(mt0, fmaxf(s[j][0], s[j][1]));
            mt1 = fmaxf(mt1, fmaxf(s[j][2], s[j][3]));
        }
        mt0 = fmaxf(mt0, __shfl_xor_sync(0xffffffffu, mt0, 1));
        mt0 = fmaxf(mt0, __shfl_xor_sync(0xffffffffu, mt0, 2));
        mt1 = fmaxf(mt1, __shfl_xor_sync(0xffffffffu, mt1, 1));
        mt1 = fmaxf(mt1, __shfl_xor_sync(0xffffffffu, mt1, 2));

        float mn0 = fmaxf(m0, mt0), mn1 = fmaxf(m1, mt1);
        float a0 = __expf(m0 - mn0), a1 = __expf(m1 - mn1);
        m0 = mn0; m1 = mn1;

        float ps0 = 0.f, ps1 = 0.f;
#pragma unroll
        for (int j = 0; j < 8; j++) {
            s[j][0] = __expf(s[j][0] - m0);
            s[j][1] = __expf(s[j][1] - m0);
            s[j][2] = __expf(s[j][2] - m1);
            s[j][3] = __expf(s[j][3] - m1);
            ps0 += s[j][0] + s[j][1];
            ps1 += s[j][2] + s[j][3];
        }
        ps0 += __shfl_xor_sync(0xffffffffu, ps0, 1);
        ps0 += __shfl_xor_sync(0xffffffffu, ps0, 2);
        ps1 += __shfl_xor_sync(0xffffffffu, ps1, 1);
        ps1 += __shfl_xor_sync(0xffffffffu, ps1, 2);
        l0 = l0 * a0 + ps0;
        l1 = l1 * a1 + ps1;

#pragma unroll
        for (int j = 0; j < 8; j++) {
            oacc[j][0] *= a0; oacc[j][1] *= a0;
            oacc[j][2] *= a1; oacc[j][3] *= a1;
        }

        // P -> Ss (own warp's 16 rows only)
#pragma unroll
        for (int j = 0; j < 8; j++) {
            *(float2*)&Ss[r0 * SLD + j * 8 + 2 * q4] =
                make_float2(f2tf32f(s[j][0]), f2tf32f(s[j][1]));
            *(float2*)&Ss[(r0 + 8) * SLD + j * 8 + 2 * q4] =
                make_float2(f2tf32f(s[j][2]), f2tf32f(s[j][3]));
        }
        __syncwarp();

        // O += P @ V
#pragma unroll
        for (int t = 0; t < 8; t++) {
            unsigned af[4];
            af[0] = __float_as_uint(Ss[r0 * SLD + t * 8 + q4]);
            af[1] = __float_as_uint(Ss[(r0 + 8) * SLD + t * 8 + q4]);
            af[2] = __float_as_uint(Ss[r0 * SLD + t * 8 + 4 + q4]);
            af[3] = __float_as_uint(Ss[(r0 + 8) * SLD + t * 8 + 4 + q4]);
#pragma unroll
            for (int j = 0; j < 8; j++) {
                unsigned bf[2];
                bf[0] = __float_as_uint(Vs[(t * 8 + q4) * SLD + j * 8 + gid]);
                bf[1] = __float_as_uint(Vs[(t * 8 + 4 + q4) * SLD + j * 8 + gid]);
                mma_tf32(oacc[j], af, bf);
            }
        }
        __syncthreads();
    }

    // Finalize
    float il0 = 1.0f / l0, il1 = 1.0f / l1;
#pragma unroll
    for (int j = 0; j < 8; j++) {
        int c = h * HD + j * 8 + 2 * q4;
        *(float2*)&O[(size_t)(b * LSEQ + q0 + r0) * CDIM + c] =
            make_float2(oacc[j][0] * il0, oacc[j][1] * il0);
        *(float2*)&O[(size_t)(b * LSEQ + q0 + r0 + 8) * CDIM + c] =
            make_float2(oacc[j][2] * il1, oacc[j][3] * il1);
    }
}

// ---------------------------------------------------------------------------
extern "C" void kernel_launch(void* const* d_in, const int* in_sizes, int n_in,
                              void* d_out, int out_size)
{
    const float* x   = (const float*)d_in[0];
    const float* wq  = (const float*)d_in[1];
    const float* wk  = (const float*)d_in[2];
    const float* wv  = (const float*)d_in[3];
    const float* wo  = (const float*)d_in[4];
    const float* qnw = (const float*)d_in[5];
    const float* knw = (const float*)d_in[6];
    float* out = (float*)d_out;

    float *pqkv, *pa;
    cudaGetSymbolAddress((void**)&pqkv, g_qkv);
    cudaGetSymbolAddress((void**)&pa, g_attn);

    // Fused QKV projection
    gemm_qkv_kernel<<<dim3(QKVD / 64, BL / 64), 128>>>(x, wq, wk, wv, pqkv);

    // Fused RMSNorm + RoPE (q + k in one launch): BL*12 warp-units
    norm_rope_kernel<<<(BL * 12 + 7) / 8, 256>>>(pqkv, qnw, knw);

    // Attention
    cudaFuncSetAttribute(attn_kernel, cudaFuncAttributeMaxDynamicSharedMemorySize,
                         (int)ATTN_SMEM);
    attn_kernel<<<dim3(LSEQ / 64, NH, BATCH), 128, ATTN_SMEM>>>(pqkv, pa);

    // Output projection
    gemm_out_kernel<<<dim3(CDIM / 64, BL / 64), 128>>>(pa, wo, out);
}

// round 5
// speedup vs baseline: 7.8699x; 1.1844x over previous
#include <cuda_runtime.h>
#include <cuda_bf16.h>
#include <math.h>

// Problem constants
#define BATCH  2
#define LSEQ   2304          // 48*48
#define CDIM   512
#define NH     8
#define NKV    4
#define HD     64
#define BL     (BATCH*LSEQ)  // 4608
#define QKVD   1024          // fused q(512) | k(256) | v(256)

// Scratch (device globals; no allocation allowed)
__device__ float g_qkv[(size_t)BL * QKVD];
__device__ float g_attn[(size_t)BL * CDIM];
__device__ float g_cos[(size_t)LSEQ * 32];
__device__ float g_sin[(size_t)LSEQ * 32];

// ---------------------------------------------------------------------------
// tf32 helpers
// ---------------------------------------------------------------------------
__device__ __forceinline__ unsigned f2tf32(float x) {
    unsigned r;
    asm("cvt.rna.tf32.f32 %0, %1;" : "=r"(r) : "f"(x));
    return r;
}
__device__ __forceinline__ float f2tf32f(float x) {
    return __uint_as_float(f2tf32(x));
}

__device__ __forceinline__ void mma_tf32(float c[4], const unsigned a[4],
                                         unsigned b0, unsigned b1) {
    asm volatile(
        "mma.sync.aligned.m16n8k8.row.col.f32.tf32.tf32.f32 "
        "{%0,%1,%2,%3}, {%4,%5,%6,%7}, {%8,%9}, {%0,%1,%2,%3};"
        : "+f"(c[0]), "+f"(c[1]), "+f"(c[2]), "+f"(c[3])
        : "r"(a[0]), "r"(a[1]), "r"(a[2]), "r"(a[3]), "r"(b0), "r"(b1));
}

// ldmatrix x4 (non-transposed): 4 8-row x 16B matrices. For 32-bit data the
// fragment mapping (thread i <- row i/4, word i%4 of matrix r) matches the
// m16n8k8 tf32 a/b fragment layouts exactly.
__device__ __forceinline__ void ldsm4(unsigned r[4], const float* p) {
    unsigned a = (unsigned)__cvta_generic_to_shared(p);
    asm volatile(
        "ldmatrix.sync.aligned.m8n8.x4.shared.b16 {%0,%1,%2,%3}, [%4];"
        : "=r"(r[0]), "=r"(r[1]), "=r"(r[2]), "=r"(r[3]) : "r"(a));
}

// ---------------------------------------------------------------------------
// tf32 GEMM tile body: C[64,64] at (bR,bColC) = A[64,K] @ B[K, 64 @bColB].
// 128 threads = 4 warps (2x2), warp tile 32x32. ldmatrix fragment feeds;
// B staged transposed (n-major) via column-strip loads. Register-pipelined.
// ---------------------------------------------------------------------------
#define ALD  20   // As row stride (16+4): rows m, cols k
#define BTLD 20   // Bts row stride: rows n, cols k

__device__ __forceinline__ void gemm_body(
    const float* __restrict__ A, int lda,
    const float* __restrict__ B, int ldb,
    float* __restrict__ C, int ldc,
    int K, int bR, int bColB, int bColC)
{
    __shared__ float As[64 * ALD];
    __shared__ float Bts[64 * BTLD];

    int tid  = threadIdx.x;
    int lane = tid & 31;
    int warp = tid >> 5;
    int wm = warp >> 1, wn = warp & 1;
    int gid = lane >> 2, q4 = lane & 3;
    int lm = lane >> 3, lr = lane & 7;       // ldmatrix: matrix id, row

    // A staging coords: rows ar, ar+32; 4 cols
    int ar = tid >> 2, ac = (tid & 3) * 4;
    // B staging: 2 column strips: n = bn, k-block bk0 / bk0+2
    int bn = tid & 63, bk0 = tid >> 6;

    float acc[2][4][4];
#pragma unroll
    for (int mi = 0; mi < 2; mi++)
#pragma unroll
        for (int nj = 0; nj < 4; nj++)
#pragma unroll
            for (int e = 0; e < 4; e++) acc[mi][nj][e] = 0.f;

    // Preload k0 = 0
    float4 ast0 = *(const float4*)&A[(size_t)(bR + ar) * lda + ac];
    float4 ast1 = *(const float4*)&A[(size_t)(bR + ar + 32) * lda + ac];
    float bst[2][4];
#pragma unroll
    for (int it = 0; it < 2; it++) {
        int k4 = bk0 + it * 2;
#pragma unroll
        for (int i = 0; i < 4; i++)
            bst[it][i] = B[(size_t)(k4 * 4 + i) * ldb + bColB + bn];
    }

    for (int k0 = 0; k0 < K; k0 += 16) {
        // Commit staged tiles (tf32-rounded)
        As[ar * ALD + ac + 0] = f2tf32f(ast0.x);
        As[ar * ALD + ac + 1] = f2tf32f(ast0.y);
        As[ar * ALD + ac + 2] = f2tf32f(ast0.z);
        As[ar * ALD + ac + 3] = f2tf32f(ast0.w);
        As[(ar + 32) * ALD + ac + 0] = f2tf32f(ast1.x);
        As[(ar + 32) * ALD + ac + 1] = f2tf32f(ast1.y);
        As[(ar + 32) * ALD + ac + 2] = f2tf32f(ast1.z);
        As[(ar + 32) * ALD + ac + 3] = f2tf32f(ast1.w);
#pragma unroll
        for (int it = 0; it < 2; it++) {
            int k4 = bk0 + it * 2;
            float4 v = make_float4(f2tf32f(bst[it][0]), f2tf32f(bst[it][1]),
                                   f2tf32f(bst[it][2]), f2tf32f(bst[it][3]));
            *(float4*)&Bts[bn * BTLD + k4 * 4] = v;
        }
        __syncthreads();

        // Prefetch next k-tile into registers
        if (k0 + 16 < K) {
            int kn = k0 + 16;
            ast0 = *(const float4*)&A[(size_t)(bR + ar) * lda + kn + ac];
            ast1 = *(const float4*)&A[(size_t)(bR + ar + 32) * lda + kn + ac];
#pragma unroll
            for (int it = 0; it < 2; it++) {
                int k4 = bk0 + it * 2;
#pragma unroll
                for (int i = 0; i < 4; i++)
                    bst[it][i] = B[(size_t)(kn + k4 * 4 + i) * ldb + bColB + bn];
            }
        }

#pragma unroll
        for (int t = 0; t < 2; t++) {
            unsigned af[2][4], bf[2][4];
#pragma unroll
            for (int mi = 0; mi < 2; mi++)
                ldsm4(af[mi], &As[(wm * 32 + mi * 16 + ((lm & 1) ? 8 : 0) + lr) * ALD
                                  + t * 8 + ((lm & 2) ? 4 : 0)]);
#pragma unroll
            for (int p = 0; p < 2; p++)
                ldsm4(bf[p], &Bts[(wn * 32 + p * 16 + ((lm & 2) ? 8 : 0) + lr) * BTLD
                                  + t * 8 + ((lm & 1) ? 4 : 0)]);
#pragma unroll
            for (int mi = 0; mi < 2; mi++)
#pragma unroll
                for (int nj = 0; nj < 4; nj++)
                    mma_tf32(acc[mi][nj], af[mi],
                             bf[nj >> 1][(nj & 1) * 2], bf[nj >> 1][(nj & 1) * 2 + 1]);
        }
        __syncthreads();
    }

#pragma unroll
    for (int mi = 0; mi < 2; mi++) {
        int r0 = bR + wm * 32 + mi * 16 + gid;
#pragma unroll
        for (int nj = 0; nj < 4; nj++) {
            int c = bColC + wn * 32 + nj * 8 + 2 * q4;
            *(float2*)&C[(size_t)r0 * ldc + c] =
                make_float2(acc[mi][nj][0], acc[mi][nj][1]);
            *(float2*)&C[(size_t)(r0 + 8) * ldc + c] =
                make_float2(acc[mi][nj][2], acc[mi][nj][3]);
        }
    }
}

__global__ __launch_bounds__(128) void gemm_qkv_kernel(
    const float* __restrict__ x, const float* __restrict__ wq,
    const float* __restrict__ wk, const float* __restrict__ wv,
    float* __restrict__ qkv)
{
    int bC = blockIdx.x * 64;
    int bR = blockIdx.y * 64;
    const float* B; int ldb, colB;
    if (bC < 512)      { B = wq; ldb = 512; colB = bC; }
    else if (bC < 768) { B = wk; ldb = 256; colB = bC - 512; }
    else               { B = wv; ldb = 256; colB = bC - 768; }
    gemm_body(x, CDIM, B, ldb, qkv, QKVD, CDIM, bR, colB, bC);
}

__global__ __launch_bounds__(128) void gemm_out_kernel(
    const float* __restrict__ A, const float* __restrict__ B,
    float* __restrict__ C)
{
    gemm_body(A, CDIM, B, CDIM, C, CDIM, CDIM, blockIdx.y * 64,
              blockIdx.x * 64, blockIdx.x * 64);
}

// ---------------------------------------------------------------------------
// RoPE trig table: cos/sin[pos][f], computed once per launch.
// ---------------------------------------------------------------------------
__global__ __launch_bounds__(32) void trig_kernel() {
    int pos = blockIdx.x, f = threadIdx.x;
    float inv_freq = powf(10000.0f, -(float)f / 32.0f);
    float s, c;
    sincosf((float)pos * inv_freq, &s, &c);
    g_cos[pos * 32 + f] = c;
    g_sin[pos * 32 + f] = s;
}

// ---------------------------------------------------------------------------
// Fused RMSNorm + RoPE: one warp per (row, head-unit); 12 units per row.
// ---------------------------------------------------------------------------
__global__ __launch_bounds__(256) void norm_rope_kernel(
    float* __restrict__ qkv, const float* __restrict__ qw,
    const float* __restrict__ kw)
{
    int u = blockIdx.x * 8 + (threadIdx.x >> 5);
    int lane = threadIdx.x & 31;
    int row = u / 12;
    int j   = u % 12;
    if (row >= BL) return;

    float* p; const float* w;
    if (j < 8) { p = qkv + (size_t)row * QKVD + j * HD;             w = qw; }
    else       { p = qkv + (size_t)row * QKVD + 512 + (j - 8) * HD; w = kw; }
    int pos = row % LSEQ;

    float x1 = p[lane], x2 = p[lane + 32];
    float ss = x1 * x1 + x2 * x2;
#pragma unroll
    for (int m = 16; m > 0; m >>= 1)
        ss += __shfl_xor_sync(0xffffffffu, ss, m);
    float inv = rsqrtf(ss * (1.0f / HD) + 1e-6f);
    float n1 = x1 * inv * w[lane];
    float n2 = x2 * inv * w[lane + 32];

    float c = g_cos[pos * 32 + lane];
    float s = g_sin[pos * 32 + lane];
    p[lane]      = n1 * c - n2 * s;
    p[lane + 32] = n1 * s + n2 * c;
}

// ---------------------------------------------------------------------------
// Flash attention, tf32 + ldmatrix. Block = 64 queries x (head, batch).
// 128 threads / 4 warps; warp owns 16 query rows; softmax in registers.
// K staged [key][dim]; V staged transposed [dim][key] via column strips.
// ---------------------------------------------------------------------------
#define SLD 68
#define ATTN_SMEM (3 * 64 * SLD * sizeof(float))

__global__ __launch_bounds__(128) void attn_kernel(
    const float* __restrict__ QKV, float* __restrict__ O)
{
    extern __shared__ float sm[];
    float* Ks = sm;                 // [key][dim]
    float* Vt = Ks + 64 * SLD;      // [dim][key]
    float* Ss = Vt + 64 * SLD;      // Q staging [q][dim], then P [q][key]

    int tid  = threadIdx.x;
    int lane = tid & 31;
    int warp = tid >> 5;
    int gid  = lane >> 2;
    int q4   = lane & 3;
    int lm   = lane >> 3, lr = lane & 7;

    int qt = blockIdx.x, h = blockIdx.y, b = blockIdx.z;
    int kvh = h >> 1;
    int q0  = qt * 64;
    int qb  = warp * 16;
    int r0  = qb + gid;

    const float* base  = QKV + (size_t)b * LSEQ * QKVD;
    const float* kbase = base + 512 + kvh * HD;
    const float* vbase = base + 768 + kvh * HD;

    // Stage Q tile (scaled, tf32) into Ss
    for (int i = tid; i < 64 * 64; i += 128) {
        int r = i >> 6, c = i & 63;
        Ss[r * SLD + c] = f2tf32f(base[(size_t)(q0 + r) * QKVD + h * HD + c] * 0.125f);
    }
    __syncthreads();

    unsigned qf[8][4];
#pragma unroll
    for (int t = 0; t < 8; t++)
        ldsm4(qf[t], &Ss[(qb + ((lm & 1) ? 8 : 0) + lr) * SLD
                         + t * 8 + ((lm & 2) ? 4 : 0)]);
    __syncthreads();

    float oacc[8][4];
#pragma unroll
    for (int j = 0; j < 8; j++)
#pragma unroll
        for (int e = 0; e < 4; e++) oacc[j][e] = 0.f;
    float m0 = -1e30f, m1 = -1e30f, l0 = 0.f, l1 = 0.f;

    // K staging coords (row-major float4): key sr+8it, dims sc..sc+3
    int sr = tid >> 4, sc = (tid & 15) * 4;
    // V staging coords (column strips): dim vd, key block vk4 = it*2 + vh
    int vd = tid & 63, vh = tid >> 6;

    float4 kst[8];
    float  vst[8][4];
#pragma unroll
    for (int it = 0; it < 8; it++) {
        kst[it] = *(const float4*)&kbase[(size_t)(sr + it * 8) * QKVD + sc];
        int k4 = it * 2 + vh;
#pragma unroll
        for (int i = 0; i < 4; i++)
            vst[it][i] = vbase[(size_t)(k4 * 4 + i) * QKVD + vd];
    }

    for (int k0 = 0; k0 < LSEQ; k0 += 64) {
        // Commit staged K/V (tf32)
#pragma unroll
        for (int it = 0; it < 8; it++) {
            int r = sr + it * 8;
            Ks[r * SLD + sc + 0] = f2tf32f(kst[it].x);
            Ks[r * SLD + sc + 1] = f2tf32f(kst[it].y);
            Ks[r * SLD + sc + 2] = f2tf32f(kst[it].z);
            Ks[r * SLD + sc + 3] = f2tf32f(kst[it].w);
            int k4 = it * 2 + vh;
            float4 v = make_float4(f2tf32f(vst[it][0]), f2tf32f(vst[it][1]),
                                   f2tf32f(vst[it][2]), f2tf32f(vst[it][3]));
            *(float4*)&Vt[vd * SLD + k4 * 4] = v;
        }
        __syncthreads();

        // Prefetch next K/V tile
        if (k0 + 64 < LSEQ) {
            int kb = k0 + 64;
#pragma unroll
            for (int it = 0; it < 8; it++) {
                kst[it] = *(const float4*)&kbase[(size_t)(kb + sr + it * 8) * QKVD + sc];
                int k4 = it * 2 + vh;
#pragma unroll
                for (int i = 0; i < 4; i++)
                    vst[it][i] = vbase[(size_t)(kb + k4 * 4 + i) * QKVD + vd];
            }
        }

        // S = (scaled Q) @ K^T  — ldmatrix feeds, t-pairs
        float s[8][4];
#pragma unroll
        for (int j = 0; j < 8; j++)
#pragma unroll
            for (int e = 0; e < 4; e++) s[j][e] = 0.f;
#pragma unroll
        for (int t = 0; t < 8; t += 2) {
#pragma unroll
            for (int j = 0; j < 8; j++) {
                unsigned bb[4];
                ldsm4(bb, &Ks[(j * 8 + lr) * SLD + t * 8
                              + ((lm & 1) ? 4 : 0) + ((lm & 2) ? 8 : 0)]);
                mma_tf32(s[j], qf[t],     bb[0], bb[1]);
                mma_tf32(s[j], qf[t + 1], bb[2], bb[3]);
            }
        }

        // Online softmax in registers
        float mt0 = -1e30f, mt1 = -1e30f;
#pragma unroll
        for (int j = 0; j < 8; j++) {
            mt0 = fmaxf(mt0, fmaxf(s[j][0], s[j][1]));
            mt1 = fmaxf(mt1, fmaxf(s[j][2], s[j][3]));
        }
        mt0 = fmaxf(mt0, __shfl_xor_sync(0xffffffffu, mt0, 1));
        mt0 = fmaxf(mt0, __shfl_xor_sync(0xffffffffu, mt0, 2));
        mt1 = fmaxf(mt1, __shfl_xor_sync(0xffffffffu, mt1, 1));
        mt1 = fmaxf(mt1, __shfl_xor_sync(0xffffffffu, mt1, 2));

        float mn0 = fmaxf(m0, mt0), mn1 = fmaxf(m1, mt1);
        float a0 = __expf(m0 - mn0), a1 = __expf(m1 - mn1);
        m0 = mn0; m1 = mn1;

        float ps0 = 0.f, ps1 = 0.f;
#pragma unroll
        for (int j = 0; j < 8; j++) {
            s[j][0] = __expf(s[j][0] - m0);
            s[j][1] = __expf(s[j][1] - m0);
            s[j][2] = __expf(s[j][2] - m1);
            s[j][3] = __expf(s[j][3] - m1);
            ps0 += s[j][0] + s[j][1];
            ps1 += s[j][2] + s[j][3];
        }
        ps0 += __shfl_xor_sync(0xffffffffu, ps0, 1);
        ps0 += __shfl_xor_sync(0xffffffffu, ps0, 2);
        ps1 += __shfl_xor_sync(0xffffffffu, ps1, 1);
        ps1 += __shfl_xor_sync(0xffffffffu, ps1, 2);
        l0 = l0 * a0 + ps0;
        l1 = l1 * a1 + ps1;

#pragma unroll
        for (int j = 0; j < 8; j++) {
            oacc[j][0] *= a0; oacc[j][1] *= a0;
            oacc[j][2] *= a1; oacc[j][3] *= a1;
        }

        // P -> Ss (own warp's 16 rows)
#pragma unroll
        for (int j = 0; j < 8; j++) {
            *(float2*)&Ss[r0 * SLD + j * 8 + 2 * q4] =
                make_float2(f2tf32f(s[j][0]), f2tf32f(s[j][1]));
            *(float2*)&Ss[(r0 + 8) * SLD + j * 8 + 2 * q4] =
                make_float2(f2tf32f(s[j][2]), f2tf32f(s[j][3]));
        }
        __syncwarp();

        // O += P @ V — ldmatrix feeds from Ss (P) and Vt
#pragma unroll
        for (int t = 0; t < 8; t += 2) {
            unsigned af0[4], af1[4];
            ldsm4(af0, &Ss[(qb + ((lm & 1) ? 8 : 0) + lr) * SLD
                           + t * 8 + ((lm & 2) ? 4 : 0)]);
            ldsm4(af1, &Ss[(qb + ((lm & 1) ? 8 : 0) + lr) * SLD
                           + (t + 1) * 8 + ((lm & 2) ? 4 : 0)]);
#pragma unroll
            for (int j = 0; j < 8; j++) {
                unsigned bb[4];
                ldsm4(bb, &Vt[(j * 8 + lr) * SLD + t * 8
                              + ((lm & 1) ? 4 : 0) + ((lm & 2) ? 8 : 0)]);
                mma_tf32(oacc[j], af0, bb[0], bb[1]);
                mma_tf32(oacc[j], af1, bb[2], bb[3]);
            }
        }
        __syncthreads();
    }

    // Finalize
    float il0 = 1.0f / l0, il1 = 1.0f / l1;
#pragma unroll
    for (int j = 0; j < 8; j++) {
        int c = h * HD + j * 8 + 2 * q4;
        *(float2*)&O[(size_t)(b * LSEQ + q0 + r0) * CDIM + c] =
            make_float2(oacc[j][0] * il0, oacc[j][1] * il0);
        *(float2*)&O[(size_t)(b * LSEQ + q0 + r0 + 8) * CDIM + c] =
            make_float2(oacc[j][2] * il1, oacc[j][3] * il1);
    }
}

// ---------------------------------------------------------------------------
extern "C" void kernel_launch(void* const* d_in, const int* in_sizes, int n_in,
                              void* d_out, int out_size)
{
    const float* x   = (const float*)d_in[0];
    const float* wq  = (const float*)d_in[1];
    const float* wk  = (const float*)d_in[2];
    const float* wv  = (const float*)d_in[3];
    const float* wo  = (const float*)d_in[4];
    const float* qnw = (const float*)d_in[5];
    const float* knw = (const float*)d_in[6];
    float* out = (float*)d_out;

    float *pqkv, *pa;
    cudaGetSymbolAddress((void**)&pqkv, g_qkv);
    cudaGetSymbolAddress((void**)&pa, g_attn);

    // RoPE trig table (independent of QKV result; runs while nothing else does,
    // cheap) + fused QKV projection
    trig_kernel<<<LSEQ, 32>>>();
    gemm_qkv_kernel<<<dim3(QKVD / 64, BL / 64), 128>>>(x, wq, wk, wv, pqkv);

    // Fused RMSNorm + RoPE (q + k)
    norm_rope_kernel<<<(BL * 12 + 7) / 8, 256>>>(pqkv, qnw, knw);

    // Attention
    cudaFuncSetAttribute(attn_kernel, cudaFuncAttributeMaxDynamicSharedMemorySize,
                         (int)ATTN_SMEM);
    attn_kernel<<<dim3(LSEQ / 64, NH, BATCH), 128, ATTN_SMEM>>>(pqkv, pa);

    // Output projection
    gemm_out_kernel<<<dim3(CDIM / 64, BL / 64), 128>>>(pa, wo, out);
}